// round 10
// baseline (speedup 1.0000x reference)
#include <cuda_runtime.h>
#include <cuda_bf16.h>
#include <cstdint>

#define EMB 64
#define IN_DIM 32
#define MAX_NODES 50000
#define MAX_EDGES 150000
#define NBINS MAX_NODES
#define SCAN_NB ((NBINS + 255) / 256)

#define NGR 16                 // e-groups of 4
#define GROWS 136              // padded GEMM-col rows per group (132 valid)
#define VPITCH 140             // fp32 V tile pitch (35 float4)

// Scratch (__device__ globals; allocation-free rule)
__device__ __nv_bfloat16 g_hhi[MAX_NODES * EMB];
__device__ __nv_bfloat16 g_hlo[MAX_NODES * EMB];
__device__ __nv_bfloat16 g_whi[NGR * GROWS * EMB];   // [g][row=d*4+e'][f]
__device__ __nv_bfloat16 g_wlo[NGR * GROWS * EMB];
__device__ float g_aggr[MAX_NODES * EMB];
__device__ int   g_src[MAX_EDGES];
__device__ int   g_tgt[MAX_EDGES];
__device__ int   g_eord[MAX_EDGES];
__device__ int   g_cnt[NBINS];
__device__ int   g_off[NBINS];     // after scatter: inclusive end offsets
__device__ int   g_bsum[SCAN_NB];
__device__ int   g_boff[SCAN_NB];
__device__ int   g_idx_is64;

__device__ __forceinline__ uint32_t smem_u32(const void* p) {
    uint32_t a;
    asm("{ .reg .u64 t; cvta.to.shared.u64 t, %1; cvt.u32.u64 %0, t; }" : "=r"(a) : "l"(p));
    return a;
}

// ---------------------------------------------------------------------------
__global__ void probe_idx_kernel(const int* __restrict__ ei32, int M) {
    int n = 2 * M;
    int is64 = 1;
    for (int i = 1; i < 256 && i < n; i += 2)
        if (ei32[i] != 0) { is64 = 0; break; }
    g_idx_is64 = is64;
}

__global__ void convert_idx_kernel(const void* __restrict__ eidx, int M) {
    int i = blockIdx.x * blockDim.x + threadIdx.x;
    if (i >= M) return;
    if (g_idx_is64) {
        const long long* p = (const long long*)eidx;
        g_src[i] = (int)p[i];
        g_tgt[i] = (int)p[M + i];
    } else {
        const int* p = (const int*)eidx;
        g_src[i] = p[i];
        g_tgt[i] = p[M + i];
    }
}

__global__ void pack_h_kernel(const float* __restrict__ h, int n) {
    int i = blockIdx.x * blockDim.x + threadIdx.x;
    if (i >= n) return;
    float v = h[i];
    __nv_bfloat16 hi = __float2bfloat16(v);
    g_hhi[i] = hi;
    g_hlo[i] = __float2bfloat16(v - __bfloat162float(hi));
}

// Row r = d*4+e' in group g covers e = 4g+e'. r>=132 -> zero pad.
// d<32 -> W[(e*64+f)*32+d] ; d==32 -> b[e*64+f]
__global__ void pack_w_kernel(const float* __restrict__ W, const float* __restrict__ b) {
    int idx = blockIdx.x * blockDim.x + threadIdx.x;
    if (idx >= NGR * GROWS * EMB) return;
    int g = idx / (GROWS * EMB);
    int rem = idx % (GROWS * EMB);
    int r = rem / EMB, f = rem % EMB;
    float w = 0.f;
    if (r < 132) {
        int d = r >> 2, ep = r & 3;
        int e = g * 4 + ep;
        w = (d < 32) ? W[(e * 64 + f) * 32 + d] : b[e * 64 + f];
    }
    __nv_bfloat16 hi = __float2bfloat16(w);
    g_whi[idx] = hi;
    g_wlo[idx] = __float2bfloat16(w - __bfloat162float(hi));
}

__global__ void init_aggr_kernel(const float* __restrict__ h, int n) {
    int i = blockIdx.x * blockDim.x + threadIdx.x;
    if (i < n) g_aggr[i] = h[i];
}

// ---------------------------------------------------------------------------
// Counting sort of edges by tgt.
__global__ void zero_cnt_kernel() {
    int i = blockIdx.x * blockDim.x + threadIdx.x;
    if (i < NBINS) g_cnt[i] = 0;
    if (i < SCAN_NB) g_bsum[i] = 0;
}

__global__ void hist_kernel(int M) {
    int i = blockIdx.x * blockDim.x + threadIdx.x;
    if (i < M) atomicAdd(&g_cnt[g_tgt[i]], 1);
}

__global__ void scanA_kernel() {
    __shared__ int buf[256];
    int b = blockIdx.x, t = threadIdx.x;
    int i = b * 256 + t;
    int v = (i < NBINS) ? g_cnt[i] : 0;
    buf[t] = v; __syncthreads();
    #pragma unroll
    for (int o = 1; o < 256; o <<= 1) {
        int u = (t >= o) ? buf[t - o] : 0;
        __syncthreads();
        buf[t] += u;
        __syncthreads();
    }
    if (i < NBINS) g_off[i] = buf[t] - v;
    if (t == 255) g_bsum[b] = buf[255];
}

__global__ void scanB_kernel() {
    __shared__ int buf[256];
    int t = threadIdx.x;
    int v = (t < SCAN_NB) ? g_bsum[t] : 0;
    buf[t] = v; __syncthreads();
    #pragma unroll
    for (int o = 1; o < 256; o <<= 1) {
        int u = (t >= o) ? buf[t - o] : 0;
        __syncthreads();
        buf[t] += u;
        __syncthreads();
    }
    if (t < SCAN_NB) g_boff[t] = buf[t] - v;
}

__global__ void scanC_kernel() {
    int i = blockIdx.x * blockDim.x + threadIdx.x;
    if (i < NBINS) g_off[i] += g_boff[i >> 8];
}

__global__ void scatter_kernel(int M) {
    int i = blockIdx.x * blockDim.x + threadIdx.x;
    if (i >= M) return;
    int pos = atomicAdd(&g_off[g_tgt[i]], 1);
    g_eord[pos] = i;
}
// After scatter: g_off[i] = inclusive end offset of node i's edge range.

// ---------------------------------------------------------------------------
// FUSED: per (node-tile 128, e-group of 4):
//   1. MMA V chunk = h(128x64) @ Wgrp(64x136) via bf16 2-term split -> regs
//   2. V chunk -> smem (overlaying staging buffers)
//   3. stage2 for this node range's edges: msg[4e] = sum_d ea_d*V[row][4d+e'] + bias
__device__ __forceinline__ void mma_bf16(float* d, const uint32_t* a, const uint32_t* b) {
    asm volatile(
        "mma.sync.aligned.m16n8k16.row.col.f32.bf16.bf16.f32 "
        "{%0,%1,%2,%3}, {%4,%5,%6,%7}, {%8,%9}, {%0,%1,%2,%3};"
        : "+f"(d[0]), "+f"(d[1]), "+f"(d[2]), "+f"(d[3])
        : "r"(a[0]), "r"(a[1]), "r"(a[2]), "r"(a[3]), "r"(b[0]), "r"(b[1]));
}
#define LDSM_X4(r0,r1,r2,r3,addr) \
    asm volatile("ldmatrix.sync.aligned.m8n8.x4.shared.b16 {%0,%1,%2,%3}, [%4];" \
        : "=r"(r0), "=r"(r1), "=r"(r2), "=r"(r3) : "r"(addr))

#define OFF_AHI 0
#define OFF_ALO 18432
#define OFF_BHI 36864          // 136 rows x 144B (+ over-read pad to 144 rows)
#define OFF_BLO 56448
#define SMEM_SZ 77184          // covers BLO + 144*144 over-read; V(71680) overlays

__global__ __launch_bounds__(256) void fused_kernel(const float* __restrict__ ea,
                                                    int N, int M)
{
    __shared__ __align__(16) char SMEM[SMEM_SZ];

    const int tid  = threadIdx.x;
    const int w    = tid >> 5;
    const int lane = tid & 31;
    const int tq   = lane >> 2;
    const int tr   = lane & 3;
    const int quad = lane >> 3;
    const int l7   = lane & 7;
    const int m0   = blockIdx.x * 128;
    const int g    = blockIdx.y;

    // Stage A planes (128 nodes x 64 f)
    const uint32_t* hh = (const uint32_t*)g_hhi;
    const uint32_t* hl = (const uint32_t*)g_hlo;
    #pragma unroll
    for (int i = 0; i < 16; i++) {
        int lin = tid + i * 256;
        int row = lin >> 5, cp = lin & 31;
        int gm = m0 + row;
        uint32_t vh = 0, vl = 0;
        if (gm < N) { vh = hh[gm * 32 + cp]; vl = hl[gm * 32 + cp]; }
        *(uint32_t*)(SMEM + OFF_AHI + row * 144 + cp * 4) = vh;
        *(uint32_t*)(SMEM + OFF_ALO + row * 144 + cp * 4) = vl;
    }
    // Stage B planes (136 rows x 64 f) for this group
    const uint32_t* wh = (const uint32_t*)g_whi;
    const uint32_t* wl = (const uint32_t*)g_wlo;
    #pragma unroll
    for (int i = 0; i < 17; i++) {
        int lin = tid + i * 256;
        if (lin < GROWS * 32) {
            int row = lin >> 5, cp = lin & 31;
            *(uint32_t*)(SMEM + OFF_BHI + row * 144 + cp * 4) = wh[(g * GROWS + row) * 32 + cp];
            *(uint32_t*)(SMEM + OFF_BLO + row * 144 + cp * 4) = wl[(g * GROWS + row) * 32 + cp];
        }
    }
    __syncthreads();

    // MMA: warp w -> m-band w*16, all 17 n-tiles
    float acc[17][4];
    #pragma unroll
    for (int j = 0; j < 17; j++)
        #pragma unroll
        for (int q = 0; q < 4; q++) acc[j][q] = 0.f;

    #pragma unroll
    for (int kk = 0; kk < 4; kk++) {
        uint32_t a[2][4];
        {
            int row  = w * 16 + (quad & 1) * 8 + l7;
            int boff = row * 144 + (kk * 16 + (quad >> 1) * 8) * 2;
            uint32_t ah = smem_u32(SMEM + OFF_AHI + boff);
            LDSM_X4(a[0][0], a[0][1], a[0][2], a[0][3], ah);
            uint32_t al = smem_u32(SMEM + OFF_ALO + boff);
            LDSM_X4(a[1][0], a[1][1], a[1][2], a[1][3], al);
        }
        #pragma unroll
        for (int jp = 0; jp < 9; jp++) {
            int col  = jp * 16 + (quad >> 1) * 8 + l7;   // jp=8 over-reads rows 136-143 (garbage -> skipped tile 17)
            int boff = col * 144 + (kk * 16 + (quad & 1) * 8) * 2;
            uint32_t bh[4], bl[4];
            uint32_t bha = smem_u32(SMEM + OFF_BHI + boff);
            LDSM_X4(bh[0], bh[1], bh[2], bh[3], bha);
            uint32_t bla = smem_u32(SMEM + OFF_BLO + boff);
            LDSM_X4(bl[0], bl[1], bl[2], bl[3], bla);
            #pragma unroll
            for (int t2 = 0; t2 < 2; t2++) {
                int j = jp * 2 + t2;
                if (j < 17) {
                    mma_bf16(acc[j], a[0], &bh[t2 * 2]);   // hi*hi
                    mma_bf16(acc[j], a[0], &bl[t2 * 2]);   // hi*lo
                    mma_bf16(acc[j], a[1], &bh[t2 * 2]);   // lo*hi
                }
            }
        }
    }

    __syncthreads();            // all LDSM reads done before overwrite
    // V chunk -> smem (overlay), rows 0..127, cols 0..135, pitch 140
    float* Vt = (float*)SMEM;
    #pragma unroll
    for (int j = 0; j < 17; j++) {
        int col  = j * 8 + 2 * tr;
        int row0 = w * 16 + tq;
        int row1 = row0 + 8;
        *(float2*)&Vt[row0 * VPITCH + col] = make_float2(acc[j][0], acc[j][1]);
        *(float2*)&Vt[row1 * VPITCH + col] = make_float2(acc[j][2], acc[j][3]);
    }
    __syncthreads();

    // Stage 2: thread per edge; CSR range from sorted edges
    int estart = (m0 == 0) ? 0 : g_off[m0 - 1];
    int last   = (m0 + 127 < N) ? (m0 + 127) : (N - 1);
    int eend   = g_off[last];
    const float4* V4 = (const float4*)SMEM;
    for (int x = estart + tid; x < eend; x += 256) {
        int m   = g_eord[x];
        int row = g_tgt[m] - m0;
        int s   = g_src[m];
        const float4* er = (const float4*)(ea + (size_t)m * 32);
        const float4* vr = V4 + row * (VPITCH / 4);
        float4 a4 = vr[32];                          // bias row d=32
        #pragma unroll
        for (int dq = 0; dq < 8; dq++) {
            float4 e4 = er[dq];
            float4 v0 = vr[dq * 4 + 0], v1 = vr[dq * 4 + 1];
            float4 v2 = vr[dq * 4 + 2], v3 = vr[dq * 4 + 3];
            a4.x += e4.x * v0.x + e4.y * v1.x + e4.z * v2.x + e4.w * v3.x;
            a4.y += e4.x * v0.y + e4.y * v1.y + e4.z * v2.y + e4.w * v3.y;
            a4.z += e4.x * v0.z + e4.y * v1.z + e4.z * v2.z + e4.w * v3.z;
            a4.w += e4.x * v0.w + e4.y * v1.w + e4.z * v2.w + e4.w * v3.w;
        }
        float* dst = g_aggr + (size_t)s * 64 + g * 4;
        atomicAdd(dst + 0, a4.x);
        atomicAdd(dst + 1, a4.y);
        atomicAdd(dst + 2, a4.z);
        atomicAdd(dst + 3, a4.w);
    }
}

// ---------------------------------------------------------------------------
__global__ void ln_kernel(const float* __restrict__ gamma,
                          const float* __restrict__ beta,
                          float* __restrict__ out, int N)
{
    int row  = blockIdx.x * 8 + (threadIdx.x >> 5);
    int lane = threadIdx.x & 31;
    if (row >= N) return;
    float x0 = g_aggr[row * 64 + lane];
    float x1 = g_aggr[row * 64 + 32 + lane];
    float s = x0 + x1;
    #pragma unroll
    for (int o = 16; o > 0; o >>= 1) s += __shfl_xor_sync(0xffffffffu, s, o);
    float mu = s * (1.f / 64.f);
    float d0 = x0 - mu, d1 = x1 - mu;
    float v = d0 * d0 + d1 * d1;
    #pragma unroll
    for (int o = 16; o > 0; o >>= 1) v += __shfl_xor_sync(0xffffffffu, v, o);
    float inv = rsqrtf(v * (1.f / 64.f) + 1e-5f);
    out[row * 64 + lane]      = d0 * inv * gamma[lane]      + beta[lane];
    out[row * 64 + 32 + lane] = d1 * inv * gamma[lane + 32] + beta[lane + 32];
}

// ---------------------------------------------------------------------------
extern "C" void kernel_launch(void* const* d_in, const int* in_sizes, int n_in,
                              void* d_out, int out_size) {
    const float* h     = (const float*)d_in[0];
    const float* ea    = (const float*)d_in[1];
    const float* W     = (const float*)d_in[2];
    const float* b     = (const float*)d_in[3];
    const float* gamma = (const float*)d_in[4];
    const float* beta  = (const float*)d_in[5];
    const void*  eidx  = d_in[6];

    int n64_seen = 0;
    for (int i = 0; i < n_in; i++) {
        switch (in_sizes[i]) {
            case 3200000: h    = (const float*)d_in[i]; break;
            case 4800000: ea   = (const float*)d_in[i]; break;
            case 131072:  W    = (const float*)d_in[i]; break;
            case 4096:    b    = (const float*)d_in[i]; break;
            case 300000:  eidx = d_in[i];               break;
            case 64:
                if (n64_seen++ == 0) gamma = (const float*)d_in[i];
                else                 beta  = (const float*)d_in[i];
                break;
            default: break;
        }
    }

    const int N = 50000;
    const int M = 150000;
    float* out = (float*)d_out;

    probe_idx_kernel<<<1, 1>>>((const int*)eidx, M);
    convert_idx_kernel<<<(M + 255) / 256, 256>>>(eidx, M);
    pack_h_kernel<<<(N * EMB + 255) / 256, 256>>>(h, N * EMB);
    pack_w_kernel<<<(NGR * GROWS * EMB + 255) / 256, 256>>>(W, b);
    init_aggr_kernel<<<(N * EMB + 255) / 256, 256>>>(h, N * EMB);
    zero_cnt_kernel<<<(NBINS + 255) / 256, 256>>>();
    hist_kernel<<<(M + 255) / 256, 256>>>(M);
    scanA_kernel<<<SCAN_NB, 256>>>();
    scanB_kernel<<<1, 256>>>();
    scanC_kernel<<<(NBINS + 255) / 256, 256>>>();
    scatter_kernel<<<(M + 255) / 256, 256>>>(M);

    dim3 gf((N + 127) / 128, NGR);                   // 391 x 16
    fused_kernel<<<gf, 256>>>(ea, N, M);

    ln_kernel<<<(N + 7) / 8, 256>>>(gamma, beta, out, N);
}

// round 11
// speedup vs baseline: 1.3180x; 1.3180x over previous
#include <cuda_runtime.h>
#include <cuda_bf16.h>
#include <cstdint>

#define EMB 64
#define IN_DIM 32
#define NKV 2112              // (IN_DIM+1)*EMB : V col c = d*64+e, d=32 -> bias
#define MAX_NODES 50000
#define MAX_EDGES 150000
#define NBINS MAX_NODES
#define SCAN_NB ((NBINS + 255) / 256)

// Scratch (__device__ globals; allocation-free rule)
__device__ __nv_bfloat16 g_hhi[MAX_NODES * EMB];
__device__ __nv_bfloat16 g_hlo[MAX_NODES * EMB];
__device__ __nv_bfloat16 g_whi[NKV * EMB];         // [c][f]
__device__ __nv_bfloat16 g_wlo[NKV * EMB];
__device__ float g_V[(size_t)MAX_NODES * NKV];
__device__ float g_aggr[MAX_NODES * EMB];
__device__ int   g_src[MAX_EDGES];
__device__ int   g_tgt[MAX_EDGES];
__device__ int   g_eord[MAX_EDGES];
__device__ int   g_cnt[NBINS];
__device__ int   g_off[NBINS];
__device__ int   g_bsum[SCAN_NB];
__device__ int   g_boff[SCAN_NB];
__device__ int   g_idx_is64;

__device__ __forceinline__ uint32_t smem_u32(const void* p) {
    uint32_t a;
    asm("{ .reg .u64 t; cvta.to.shared.u64 t, %1; cvt.u32.u64 %0, t; }" : "=r"(a) : "l"(p));
    return a;
}

// ---------------------------------------------------------------------------
__global__ void probe_idx_kernel(const int* __restrict__ ei32, int M) {
    int n = 2 * M;
    int is64 = 1;
    for (int i = 1; i < 256 && i < n; i += 2)
        if (ei32[i] != 0) { is64 = 0; break; }
    g_idx_is64 = is64;
}

__global__ void convert_idx_kernel(const void* __restrict__ eidx, int M) {
    int i = blockIdx.x * blockDim.x + threadIdx.x;
    if (i >= M) return;
    if (g_idx_is64) {
        const long long* p = (const long long*)eidx;
        g_src[i] = (int)p[i];
        g_tgt[i] = (int)p[M + i];
    } else {
        const int* p = (const int*)eidx;
        g_src[i] = p[i];
        g_tgt[i] = p[M + i];
    }
}

// Fused: bf16-split h AND residual init of aggr (h read once).
__global__ void pack_h_init_kernel(const float* __restrict__ h, int n) {
    int i = blockIdx.x * blockDim.x + threadIdx.x;
    if (i >= n) return;
    float v = h[i];
    __nv_bfloat16 hi = __float2bfloat16(v);
    g_hhi[i] = hi;
    g_hlo[i] = __float2bfloat16(v - __bfloat162float(hi));
    g_aggr[i] = v;
}

// col c=(d,e): d<32 -> W[(e*64+f)*32+d] ; d==32 -> b[e*64+f]
// Also zeroes the sort histograms (saves a launch).
__global__ void pack_w_zero_kernel(const float* __restrict__ W, const float* __restrict__ b) {
    int idx = blockIdx.x * blockDim.x + threadIdx.x;
    if (idx < NBINS) g_cnt[idx] = 0;
    if (idx < SCAN_NB) g_bsum[idx] = 0;
    if (idx >= NKV * EMB) return;
    int c = idx >> 6, f = idx & 63;
    int d = c >> 6, e = c & 63;
    float w = (d < 32) ? W[(e * 64 + f) * 32 + d] : b[e * 64 + f];
    __nv_bfloat16 hi = __float2bfloat16(w);
    g_whi[idx] = hi;
    g_wlo[idx] = __float2bfloat16(w - __bfloat162float(hi));
}

// ---------------------------------------------------------------------------
// Stage 1: V = h @ W3T via mma.sync m16n8k16 bf16 (2-term split), smem+ldmatrix.
// Block 128 nodes x 128 cols, 8 warps (4m x 2n), warp tile 32 x 64. (R8 verbatim)
__device__ __forceinline__ void mma_bf16(float* d, const uint32_t* a, const uint32_t* b) {
    asm volatile(
        "mma.sync.aligned.m16n8k16.row.col.f32.bf16.bf16.f32 "
        "{%0,%1,%2,%3}, {%4,%5,%6,%7}, {%8,%9}, {%0,%1,%2,%3};"
        : "+f"(d[0]), "+f"(d[1]), "+f"(d[2]), "+f"(d[3])
        : "r"(a[0]), "r"(a[1]), "r"(a[2]), "r"(a[3]), "r"(b[0]), "r"(b[1]));
}
#define LDSM_X4(r0,r1,r2,r3,addr) \
    asm volatile("ldmatrix.sync.aligned.m8n8.x4.shared.b16 {%0,%1,%2,%3}, [%4];" \
        : "=r"(r0), "=r"(r1), "=r"(r2), "=r"(r3) : "r"(addr))

#define SPITCH 72             // bf16 per smem row (144 bytes)

__global__ __launch_bounds__(256) void node_v_mma_kernel(int N)
{
    __shared__ __align__(16) __nv_bfloat16 sA[2][128 * SPITCH];
    __shared__ __align__(16) __nv_bfloat16 sB[2][128 * SPITCH];

    const int tid  = threadIdx.x;
    const int w    = tid >> 5;
    const int lane = tid & 31;
    const int tq   = lane >> 2;
    const int tr   = lane & 3;
    const int m0   = blockIdx.x * 128;
    const int n0   = blockIdx.y * 128;

    const uint32_t* hh = (const uint32_t*)g_hhi;
    const uint32_t* hl = (const uint32_t*)g_hlo;
    const uint32_t* wh = (const uint32_t*)g_whi;
    const uint32_t* wl = (const uint32_t*)g_wlo;
    #pragma unroll
    for (int i = 0; i < 16; i++) {
        int lin = tid + i * 256;
        int row = lin >> 5, cp = lin & 31;
        int gm = m0 + row;
        uint32_t vh = 0, vl = 0;
        if (gm < N) { vh = hh[gm * 32 + cp]; vl = hl[gm * 32 + cp]; }
        *(uint32_t*)((char*)&sA[0][0] + row * 144 + cp * 4) = vh;
        *(uint32_t*)((char*)&sA[1][0] + row * 144 + cp * 4) = vl;
    }
    #pragma unroll
    for (int i = 0; i < 16; i++) {
        int lin = tid + i * 256;
        int row = lin >> 5, cp = lin & 31;
        int gc = n0 + row;
        uint32_t vh = 0, vl = 0;
        if (gc < NKV) { vh = wh[gc * 32 + cp]; vl = wl[gc * 32 + cp]; }
        *(uint32_t*)((char*)&sB[0][0] + row * 144 + cp * 4) = vh;
        *(uint32_t*)((char*)&sB[1][0] + row * 144 + cp * 4) = vl;
    }
    __syncthreads();

    const int mband = (w & 3) * 32;
    const int nband = (w >> 2) * 64;
    const int quad  = lane >> 3;
    const int l7    = lane & 7;

    float acc[2][8][4];
    #pragma unroll
    for (int mt = 0; mt < 2; mt++)
        #pragma unroll
        for (int j = 0; j < 8; j++)
            #pragma unroll
            for (int q = 0; q < 4; q++) acc[mt][j][q] = 0.f;

    #pragma unroll
    for (int kk = 0; kk < 4; kk++) {
        uint32_t a[2][2][4];
        #pragma unroll
        for (int mt = 0; mt < 2; mt++) {
            int row  = mband + mt * 16 + (quad & 1) * 8 + l7;
            int boff = row * 144 + (kk * 16 + (quad >> 1) * 8) * 2;
            #pragma unroll
            for (int pl = 0; pl < 2; pl++) {
                uint32_t addr = smem_u32((const char*)&sA[pl][0] + boff);
                LDSM_X4(a[pl][mt][0], a[pl][mt][1], a[pl][mt][2], a[pl][mt][3], addr);
            }
        }
        #pragma unroll
        for (int jp = 0; jp < 4; jp++) {
            int col  = nband + jp * 16 + (quad >> 1) * 8 + l7;
            int boff = col * 144 + (kk * 16 + (quad & 1) * 8) * 2;
            uint32_t bh[4], bl[4];
            uint32_t ah = smem_u32((const char*)&sB[0][0] + boff);
            LDSM_X4(bh[0], bh[1], bh[2], bh[3], ah);
            uint32_t al = smem_u32((const char*)&sB[1][0] + boff);
            LDSM_X4(bl[0], bl[1], bl[2], bl[3], al);
            #pragma unroll
            for (int t2 = 0; t2 < 2; t2++) {
                int j = jp * 2 + t2;
                #pragma unroll
                for (int mt = 0; mt < 2; mt++) {
                    mma_bf16(acc[mt][j], a[0][mt], &bh[t2 * 2]);   // hi*hi
                    mma_bf16(acc[mt][j], a[0][mt], &bl[t2 * 2]);   // hi*lo
                    mma_bf16(acc[mt][j], a[1][mt], &bh[t2 * 2]);   // lo*hi
                }
            }
        }
    }

    // Direct epilogue (R8 — measured best)
    #pragma unroll
    for (int mt = 0; mt < 2; mt++) {
        #pragma unroll
        for (int half = 0; half < 2; half++) {
            int gm = m0 + mband + mt * 16 + half * 8 + tq;
            if (gm >= N) continue;
            float* vrow = g_V + (size_t)gm * NKV;
            #pragma unroll
            for (int j = 0; j < 8; j++) {
                int gc = n0 + nband + j * 8 + 2 * tr;
                if (gc >= NKV) continue;
                float2 v;
                v.x = acc[mt][j][half * 2 + 0];
                v.y = acc[mt][j][half * 2 + 1];
                *(float2*)(vrow + gc) = v;
            }
        }
    }
}

// ---------------------------------------------------------------------------
// Counting sort of edges by tgt.
__global__ void hist_kernel(int M) {
    int i = blockIdx.x * blockDim.x + threadIdx.x;
    if (i < M) atomicAdd(&g_cnt[g_tgt[i]], 1);
}

__global__ void scanA_kernel() {
    __shared__ int buf[256];
    int b = blockIdx.x, t = threadIdx.x;
    int i = b * 256 + t;
    int v = (i < NBINS) ? g_cnt[i] : 0;
    buf[t] = v; __syncthreads();
    #pragma unroll
    for (int o = 1; o < 256; o <<= 1) {
        int u = (t >= o) ? buf[t - o] : 0;
        __syncthreads();
        buf[t] += u;
        __syncthreads();
    }
    if (i < NBINS) g_off[i] = buf[t] - v;
    if (t == 255) g_bsum[b] = buf[255];
}

__global__ void scanB_kernel() {
    __shared__ int buf[256];
    int t = threadIdx.x;
    int v = (t < SCAN_NB) ? g_bsum[t] : 0;
    buf[t] = v; __syncthreads();
    #pragma unroll
    for (int o = 1; o < 256; o <<= 1) {
        int u = (t >= o) ? buf[t - o] : 0;
        __syncthreads();
        buf[t] += u;
        __syncthreads();
    }
    if (t < SCAN_NB) g_boff[t] = buf[t] - v;
}

__global__ void scanC_kernel() {
    int i = blockIdx.x * blockDim.x + threadIdx.x;
    if (i < NBINS) g_off[i] += g_boff[i >> 8];
}

__global__ void scatter_kernel(int M) {
    int i = blockIdx.x * blockDim.x + threadIdx.x;
    if (i >= M) return;
    int pos = atomicAdd(&g_off[g_tgt[i]], 1);
    g_eord[pos] = i;
}

// ---------------------------------------------------------------------------
// Stage 2: warp per edge (sorted by tgt). float4 loads, d split by lane half.
__global__ __launch_bounds__(256) void edge_msg_kernel(const float* __restrict__ ea, int M)
{
    int w    = blockIdx.x * 8 + (threadIdx.x >> 5);
    int lane = threadIdx.x & 31;
    if (w >= M) return;
    int m = g_eord[w];

    const int half = lane >> 4;        // 0: even d, 1: odd d
    const int q    = lane & 15;        // owns cols q*4 .. q*4+3

    float eav = ea[(size_t)m * 32 + lane];
    int t = g_tgt[m], s = g_src[m];
    const float4* Vt = (const float4*)(g_V + (size_t)t * NKV);

    float4 acc = make_float4(0.f, 0.f, 0.f, 0.f);
    #pragma unroll
    for (int dd = 0; dd < 16; dd++) {
        int d = dd * 2 + half;
        float4 v = Vt[d * 16 + q];
        float a = __shfl_sync(0xffffffffu, eav, d);
        acc.x += a * v.x; acc.y += a * v.y; acc.z += a * v.z; acc.w += a * v.w;
    }
    if (half == 0) {                   // bias row d=32, add once
        float4 vb = Vt[32 * 16 + q];
        acc.x += vb.x; acc.y += vb.y; acc.z += vb.z; acc.w += vb.w;
    }
    acc.x += __shfl_xor_sync(0xffffffffu, acc.x, 16);
    acc.y += __shfl_xor_sync(0xffffffffu, acc.y, 16);
    acc.z += __shfl_xor_sync(0xffffffffu, acc.z, 16);
    acc.w += __shfl_xor_sync(0xffffffffu, acc.w, 16);

    float* base = &g_aggr[(size_t)s * 64 + q * 4];
    if (half == 0) { atomicAdd(base + 0, acc.x); atomicAdd(base + 1, acc.y); }
    else           { atomicAdd(base + 2, acc.z); atomicAdd(base + 3, acc.w); }
}

// ---------------------------------------------------------------------------
__global__ void ln_kernel(const float* __restrict__ gamma,
                          const float* __restrict__ beta,
                          float* __restrict__ out, int N)
{
    int row  = blockIdx.x * 8 + (threadIdx.x >> 5);
    int lane = threadIdx.x & 31;
    if (row >= N) return;
    float x0 = g_aggr[row * 64 + lane];
    float x1 = g_aggr[row * 64 + 32 + lane];
    float s = x0 + x1;
    #pragma unroll
    for (int o = 16; o > 0; o >>= 1) s += __shfl_xor_sync(0xffffffffu, s, o);
    float mu = s * (1.f / 64.f);
    float d0 = x0 - mu, d1 = x1 - mu;
    float v = d0 * d0 + d1 * d1;
    #pragma unroll
    for (int o = 16; o > 0; o >>= 1) v += __shfl_xor_sync(0xffffffffu, v, o);
    float inv = rsqrtf(v * (1.f / 64.f) + 1e-5f);
    out[row * 64 + lane]      = d0 * inv * gamma[lane]      + beta[lane];
    out[row * 64 + 32 + lane] = d1 * inv * gamma[lane + 32] + beta[lane + 32];
}

// ---------------------------------------------------------------------------
extern "C" void kernel_launch(void* const* d_in, const int* in_sizes, int n_in,
                              void* d_out, int out_size) {
    const float* h     = (const float*)d_in[0];
    const float* ea    = (const float*)d_in[1];
    const float* W     = (const float*)d_in[2];
    const float* b     = (const float*)d_in[3];
    const float* gamma = (const float*)d_in[4];
    const float* beta  = (const float*)d_in[5];
    const void*  eidx  = d_in[6];

    int n64_seen = 0;
    for (int i = 0; i < n_in; i++) {
        switch (in_sizes[i]) {
            case 3200000: h    = (const float*)d_in[i]; break;
            case 4800000: ea   = (const float*)d_in[i]; break;
            case 131072:  W    = (const float*)d_in[i]; break;
            case 4096:    b    = (const float*)d_in[i]; break;
            case 300000:  eidx = d_in[i];               break;
            case 64:
                if (n64_seen++ == 0) gamma = (const float*)d_in[i];
                else                 beta  = (const float*)d_in[i];
                break;
            default: break;
        }
    }

    const int N = 50000;
    const int M = 150000;
    float* out = (float*)d_out;

    probe_idx_kernel<<<1, 1>>>((const int*)eidx, M);                     // 1
    pack_h_init_kernel<<<(N * EMB + 255) / 256, 256>>>(h, N * EMB);      // 2
    pack_w_zero_kernel<<<(NKV * EMB + 255) / 256, 256>>>(W, b);          // 3

    dim3 g1((N + 127) / 128, (NKV + 127) / 128);                         // 391 x 17
    node_v_mma_kernel<<<g1, 256>>>(N);                                   // 4 (profiled slot)

    convert_idx_kernel<<<(M + 255) / 256, 256>>>(eidx, M);
    hist_kernel<<<(M + 255) / 256, 256>>>(M);
    scanA_kernel<<<SCAN_NB, 256>>>();
    scanB_kernel<<<1, 256>>>();
    scanC_kernel<<<(NBINS + 255) / 256, 256>>>();
    scatter_kernel<<<(M + 255) / 256, 256>>>(M);

    edge_msg_kernel<<<(M + 7) / 8, 256>>>(ea, M);
    ln_kernel<<<(N + 7) / 8, 256>>>(gamma, beta, out, N);
}

// round 12
// speedup vs baseline: 1.4704x; 1.1157x over previous
#include <cuda_runtime.h>
#include <cuda_bf16.h>
#include <cuda_fp16.h>
#include <cstdint>

#define EMB 64
#define IN_DIM 32
#define NKV 2112              // (IN_DIM+1)*EMB : V col c = d*64+e, d=32 -> bias
#define MAX_NODES 50000
#define MAX_EDGES 150000
#define NBINS MAX_NODES
#define SCAN_NB ((NBINS + 255) / 256)

// Scratch (__device__ globals; allocation-free rule)
__device__ __nv_bfloat16 g_hhi[MAX_NODES * EMB];
__device__ __nv_bfloat16 g_hlo[MAX_NODES * EMB];
__device__ __nv_bfloat16 g_whi[NKV * EMB];         // [c][f]
__device__ __nv_bfloat16 g_wlo[NKV * EMB];
__device__ __half g_V[(size_t)MAX_NODES * NKV];    // fp16 V (~211 MB)
__device__ float g_aggr[MAX_NODES * EMB];
__device__ int   g_src[MAX_EDGES];
__device__ int   g_tgt[MAX_EDGES];
__device__ int   g_eord[MAX_EDGES];
__device__ int   g_cnt[NBINS];
__device__ int   g_off[NBINS];
__device__ int   g_bsum[SCAN_NB];
__device__ int   g_boff[SCAN_NB];
__device__ int   g_idx_is64;

__device__ __forceinline__ uint32_t smem_u32(const void* p) {
    uint32_t a;
    asm("{ .reg .u64 t; cvta.to.shared.u64 t, %1; cvt.u32.u64 %0, t; }" : "=r"(a) : "l"(p));
    return a;
}

// ---------------------------------------------------------------------------
__global__ void probe_idx_kernel(const int* __restrict__ ei32, int M) {
    int n = 2 * M;
    int is64 = 1;
    for (int i = 1; i < 256 && i < n; i += 2)
        if (ei32[i] != 0) { is64 = 0; break; }
    g_idx_is64 = is64;
}

__global__ void convert_idx_kernel(const void* __restrict__ eidx, int M) {
    int i = blockIdx.x * blockDim.x + threadIdx.x;
    if (i >= M) return;
    if (g_idx_is64) {
        const long long* p = (const long long*)eidx;
        g_src[i] = (int)p[i];
        g_tgt[i] = (int)p[M + i];
    } else {
        const int* p = (const int*)eidx;
        g_src[i] = p[i];
        g_tgt[i] = p[M + i];
    }
}

// Fused: bf16-split h AND residual init of aggr (h read once).
__global__ void pack_h_init_kernel(const float* __restrict__ h, int n) {
    int i = blockIdx.x * blockDim.x + threadIdx.x;
    if (i >= n) return;
    float v = h[i];
    __nv_bfloat16 hi = __float2bfloat16(v);
    g_hhi[i] = hi;
    g_hlo[i] = __float2bfloat16(v - __bfloat162float(hi));
    g_aggr[i] = v;
}

// col c=(d,e): d<32 -> W[(e*64+f)*32+d] ; d==32 -> b[e*64+f]
// Also zeroes the sort histograms (saves a launch).
__global__ void pack_w_zero_kernel(const float* __restrict__ W, const float* __restrict__ b) {
    int idx = blockIdx.x * blockDim.x + threadIdx.x;
    if (idx < NBINS) g_cnt[idx] = 0;
    if (idx < SCAN_NB) g_bsum[idx] = 0;
    if (idx >= NKV * EMB) return;
    int c = idx >> 6, f = idx & 63;
    int d = c >> 6, e = c & 63;
    float w = (d < 32) ? W[(e * 64 + f) * 32 + d] : b[e * 64 + f];
    __nv_bfloat16 hi = __float2bfloat16(w);
    g_whi[idx] = hi;
    g_wlo[idx] = __float2bfloat16(w - __bfloat162float(hi));
}

// ---------------------------------------------------------------------------
// Stage 1: V = h @ W3T via mma.sync m16n8k16 bf16 (2-term split), smem+ldmatrix.
// Block 128 nodes x 128 cols, 8 warps (4m x 2n), warp tile 32 x 64.
// Epilogue converts fp32 acc -> fp16 (half2 stores).
__device__ __forceinline__ void mma_bf16(float* d, const uint32_t* a, const uint32_t* b) {
    asm volatile(
        "mma.sync.aligned.m16n8k16.row.col.f32.bf16.bf16.f32 "
        "{%0,%1,%2,%3}, {%4,%5,%6,%7}, {%8,%9}, {%0,%1,%2,%3};"
        : "+f"(d[0]), "+f"(d[1]), "+f"(d[2]), "+f"(d[3])
        : "r"(a[0]), "r"(a[1]), "r"(a[2]), "r"(a[3]), "r"(b[0]), "r"(b[1]));
}
#define LDSM_X4(r0,r1,r2,r3,addr) \
    asm volatile("ldmatrix.sync.aligned.m8n8.x4.shared.b16 {%0,%1,%2,%3}, [%4];" \
        : "=r"(r0), "=r"(r1), "=r"(r2), "=r"(r3) : "r"(addr))

#define SPITCH 72             // bf16 per smem row (144 bytes)

__global__ __launch_bounds__(256) void node_v_mma_kernel(int N)
{
    __shared__ __align__(16) __nv_bfloat16 sA[2][128 * SPITCH];
    __shared__ __align__(16) __nv_bfloat16 sB[2][128 * SPITCH];

    const int tid  = threadIdx.x;
    const int w    = tid >> 5;
    const int lane = tid & 31;
    const int tq   = lane >> 2;
    const int tr   = lane & 3;
    const int m0   = blockIdx.x * 128;
    const int n0   = blockIdx.y * 128;

    const uint32_t* hh = (const uint32_t*)g_hhi;
    const uint32_t* hl = (const uint32_t*)g_hlo;
    const uint32_t* wh = (const uint32_t*)g_whi;
    const uint32_t* wl = (const uint32_t*)g_wlo;
    #pragma unroll
    for (int i = 0; i < 16; i++) {
        int lin = tid + i * 256;
        int row = lin >> 5, cp = lin & 31;
        int gm = m0 + row;
        uint32_t vh = 0, vl = 0;
        if (gm < N) { vh = hh[gm * 32 + cp]; vl = hl[gm * 32 + cp]; }
        *(uint32_t*)((char*)&sA[0][0] + row * 144 + cp * 4) = vh;
        *(uint32_t*)((char*)&sA[1][0] + row * 144 + cp * 4) = vl;
    }
    #pragma unroll
    for (int i = 0; i < 16; i++) {
        int lin = tid + i * 256;
        int row = lin >> 5, cp = lin & 31;
        int gc = n0 + row;
        uint32_t vh = 0, vl = 0;
        if (gc < NKV) { vh = wh[gc * 32 + cp]; vl = wl[gc * 32 + cp]; }
        *(uint32_t*)((char*)&sB[0][0] + row * 144 + cp * 4) = vh;
        *(uint32_t*)((char*)&sB[1][0] + row * 144 + cp * 4) = vl;
    }
    __syncthreads();

    const int mband = (w & 3) * 32;
    const int nband = (w >> 2) * 64;
    const int quad  = lane >> 3;
    const int l7    = lane & 7;

    float acc[2][8][4];
    #pragma unroll
    for (int mt = 0; mt < 2; mt++)
        #pragma unroll
        for (int j = 0; j < 8; j++)
            #pragma unroll
            for (int q = 0; q < 4; q++) acc[mt][j][q] = 0.f;

    #pragma unroll
    for (int kk = 0; kk < 4; kk++) {
        uint32_t a[2][2][4];
        #pragma unroll
        for (int mt = 0; mt < 2; mt++) {
            int row  = mband + mt * 16 + (quad & 1) * 8 + l7;
            int boff = row * 144 + (kk * 16 + (quad >> 1) * 8) * 2;
            #pragma unroll
            for (int pl = 0; pl < 2; pl++) {
                uint32_t addr = smem_u32((const char*)&sA[pl][0] + boff);
                LDSM_X4(a[pl][mt][0], a[pl][mt][1], a[pl][mt][2], a[pl][mt][3], addr);
            }
        }
        #pragma unroll
        for (int jp = 0; jp < 4; jp++) {
            int col  = nband + jp * 16 + (quad >> 1) * 8 + l7;
            int boff = col * 144 + (kk * 16 + (quad & 1) * 8) * 2;
            uint32_t bh[4], bl[4];
            uint32_t ah = smem_u32((const char*)&sB[0][0] + boff);
            LDSM_X4(bh[0], bh[1], bh[2], bh[3], ah);
            uint32_t al = smem_u32((const char*)&sB[1][0] + boff);
            LDSM_X4(bl[0], bl[1], bl[2], bl[3], al);
            #pragma unroll
            for (int t2 = 0; t2 < 2; t2++) {
                int j = jp * 2 + t2;
                #pragma unroll
                for (int mt = 0; mt < 2; mt++) {
                    mma_bf16(acc[mt][j], a[0][mt], &bh[t2 * 2]);   // hi*hi
                    mma_bf16(acc[mt][j], a[0][mt], &bl[t2 * 2]);   // hi*lo
                    mma_bf16(acc[mt][j], a[1][mt], &bh[t2 * 2]);   // lo*hi
                }
            }
        }
    }

    // Direct epilogue, fp16 half2 stores
    #pragma unroll
    for (int mt = 0; mt < 2; mt++) {
        #pragma unroll
        for (int half = 0; half < 2; half++) {
            int gm = m0 + mband + mt * 16 + half * 8 + tq;
            if (gm >= N) continue;
            __half* vrow = g_V + (size_t)gm * NKV;
            #pragma unroll
            for (int j = 0; j < 8; j++) {
                int gc = n0 + nband + j * 8 + 2 * tr;
                if (gc >= NKV) continue;
                __half2 v = __floats2half2_rn(acc[mt][j][half * 2 + 0],
                                              acc[mt][j][half * 2 + 1]);
                *(__half2*)(vrow + gc) = v;
            }
        }
    }
}

// ---------------------------------------------------------------------------
// Counting sort of edges by tgt.
__global__ void hist_kernel(int M) {
    int i = blockIdx.x * blockDim.x + threadIdx.x;
    if (i < M) atomicAdd(&g_cnt[g_tgt[i]], 1);
}

__global__ void scanA_kernel() {
    __shared__ int buf[256];
    int b = blockIdx.x, t = threadIdx.x;
    int i = b * 256 + t;
    int v = (i < NBINS) ? g_cnt[i] : 0;
    buf[t] = v; __syncthreads();
    #pragma unroll
    for (int o = 1; o < 256; o <<= 1) {
        int u = (t >= o) ? buf[t - o] : 0;
        __syncthreads();
        buf[t] += u;
        __syncthreads();
    }
    if (i < NBINS) g_off[i] = buf[t] - v;
    if (t == 255) g_bsum[b] = buf[255];
}

__global__ void scanB_kernel() {
    __shared__ int buf[256];
    int t = threadIdx.x;
    int v = (t < SCAN_NB) ? g_bsum[t] : 0;
    buf[t] = v; __syncthreads();
    #pragma unroll
    for (int o = 1; o < 256; o <<= 1) {
        int u = (t >= o) ? buf[t - o] : 0;
        __syncthreads();
        buf[t] += u;
        __syncthreads();
    }
    if (t < SCAN_NB) g_boff[t] = buf[t] - v;
}

__global__ void scanC_kernel() {
    int i = blockIdx.x * blockDim.x + threadIdx.x;
    if (i < NBINS) g_off[i] += g_boff[i >> 8];
}

__global__ void scatter_kernel(int M) {
    int i = blockIdx.x * blockDim.x + threadIdx.x;
    if (i >= M) return;
    int pos = atomicAdd(&g_off[g_tgt[i]], 1);
    g_eord[pos] = i;
}

// ---------------------------------------------------------------------------
// Stage 2: warp per edge (sorted by tgt). fp16 V, uint2 (4-half) loads.
__global__ __launch_bounds__(256) void edge_msg_kernel(const float* __restrict__ ea, int M)
{
    int w    = blockIdx.x * 8 + (threadIdx.x >> 5);
    int lane = threadIdx.x & 31;
    if (w >= M) return;
    int m = g_eord[w];

    const int half = lane >> 4;        // 0: even d, 1: odd d
    const int q    = lane & 15;        // owns cols q*4 .. q*4+3

    float eav = ea[(size_t)m * 32 + lane];
    int t = g_tgt[m], s = g_src[m];
    const uint2* Vt = (const uint2*)(g_V + (size_t)t * NKV);   // uint2 = 4 halfs

    float4 acc = make_float4(0.f, 0.f, 0.f, 0.f);
    #pragma unroll
    for (int dd = 0; dd < 16; dd++) {
        int d = dd * 2 + half;
        uint2 u = Vt[d * 16 + q];
        float2 v01 = __half22float2(*(const __half2*)&u.x);
        float2 v23 = __half22float2(*(const __half2*)&u.y);
        float a = __shfl_sync(0xffffffffu, eav, d);
        acc.x += a * v01.x; acc.y += a * v01.y;
        acc.z += a * v23.x; acc.w += a * v23.y;
    }
    if (half == 0) {                   // bias row d=32, add once
        uint2 u = Vt[32 * 16 + q];
        float2 v01 = __half22float2(*(const __half2*)&u.x);
        float2 v23 = __half22float2(*(const __half2*)&u.y);
        acc.x += v01.x; acc.y += v01.y; acc.z += v23.x; acc.w += v23.y;
    }
    acc.x += __shfl_xor_sync(0xffffffffu, acc.x, 16);
    acc.y += __shfl_xor_sync(0xffffffffu, acc.y, 16);
    acc.z += __shfl_xor_sync(0xffffffffu, acc.z, 16);
    acc.w += __shfl_xor_sync(0xffffffffu, acc.w, 16);

    float* base = &g_aggr[(size_t)s * 64 + q * 4];
    if (half == 0) { atomicAdd(base + 0, acc.x); atomicAdd(base + 1, acc.y); }
    else           { atomicAdd(base + 2, acc.z); atomicAdd(base + 3, acc.w); }
}

// ---------------------------------------------------------------------------
__global__ void ln_kernel(const float* __restrict__ gamma,
                          const float* __restrict__ beta,
                          float* __restrict__ out, int N)
{
    int row  = blockIdx.x * 8 + (threadIdx.x >> 5);
    int lane = threadIdx.x & 31;
    if (row >= N) return;
    float x0 = g_aggr[row * 64 + lane];
    float x1 = g_aggr[row * 64 + 32 + lane];
    float s = x0 + x1;
    #pragma unroll
    for (int o = 16; o > 0; o >>= 1) s += __shfl_xor_sync(0xffffffffu, s, o);
    float mu = s * (1.f / 64.f);
    float d0 = x0 - mu, d1 = x1 - mu;
    float v = d0 * d0 + d1 * d1;
    #pragma unroll
    for (int o = 16; o > 0; o >>= 1) v += __shfl_xor_sync(0xffffffffu, v, o);
    float inv = rsqrtf(v * (1.f / 64.f) + 1e-5f);
    out[row * 64 + lane]      = d0 * inv * gamma[lane]      + beta[lane];
    out[row * 64 + 32 + lane] = d1 * inv * gamma[lane + 32] + beta[lane + 32];
}

// ---------------------------------------------------------------------------
extern "C" void kernel_launch(void* const* d_in, const int* in_sizes, int n_in,
                              void* d_out, int out_size) {
    const float* h     = (const float*)d_in[0];
    const float* ea    = (const float*)d_in[1];
    const float* W     = (const float*)d_in[2];
    const float* b     = (const float*)d_in[3];
    const float* gamma = (const float*)d_in[4];
    const float* beta  = (const float*)d_in[5];
    const void*  eidx  = d_in[6];

    int n64_seen = 0;
    for (int i = 0; i < n_in; i++) {
        switch (in_sizes[i]) {
            case 3200000: h    = (const float*)d_in[i]; break;
            case 4800000: ea   = (const float*)d_in[i]; break;
            case 131072:  W    = (const float*)d_in[i]; break;
            case 4096:    b    = (const float*)d_in[i]; break;
            case 300000:  eidx = d_in[i];               break;
            case 64:
                if (n64_seen++ == 0) gamma = (const float*)d_in[i];
                else                 beta  = (const float*)d_in[i];
                break;
            default: break;
        }
    }

    const int N = 50000;
    const int M = 150000;
    float* out = (float*)d_out;

    probe_idx_kernel<<<1, 1>>>((const int*)eidx, M);                     // 1
    pack_h_init_kernel<<<(N * EMB + 255) / 256, 256>>>(h, N * EMB);      // 2
    pack_w_zero_kernel<<<(NKV * EMB + 255) / 256, 256>>>(W, b);          // 3

    dim3 g1((N + 127) / 128, (NKV + 127) / 128);                         // 391 x 17
    node_v_mma_kernel<<<g1, 256>>>(N);                                   // 4 (profiled slot)

    convert_idx_kernel<<<(M + 255) / 256, 256>>>(eidx, M);
    hist_kernel<<<(M + 255) / 256, 256>>>(M);
    scanA_kernel<<<SCAN_NB, 256>>>();
    scanB_kernel<<<1, 256>>>();
    scanC_kernel<<<(NBINS + 255) / 256, 256>>>();
    scatter_kernel<<<(M + 255) / 256, 256>>>(M);

    edge_msg_kernel<<<(M + 7) / 8, 256>>>(ea, M);
    ln_kernel<<<(N + 7) / 8, 256>>>(gamma, beta, out, N);
}